// round 2
// baseline (speedup 1.0000x reference)
#include <cuda_runtime.h>
#include <cuda_fp16.h>
#include <mma.h>
#include <cstdint>
#include <cstddef>

using namespace nvcuda;

#define NN    8192
#define IND   256
#define HH    128
#define NL    3
#define NNET  3

// ---------------- device scratch (static, allowed) ----------------
__device__ __align__(16) __half g_A16[(size_t)NNET * NN * NN];   // 402 MB fp16 adj cache
__device__ __align__(16) __half g_X16[NN * IND];
__device__ __align__(16) __half g_Wi16[IND * HH];
__device__ __align__(16) __half g_Wm16[NL * HH * HH];
__device__ __align__(16) __half g_Wu16[NL * 2 * HH * HH];
__device__ __align__(16) __half g_h016[NN * HH];
__device__ __align__(16) __half g_msg16[NN * HH];
__device__ __align__(16) __half g_comb[NN * 2 * HH];             // [h | msg@Wm] fp16
__device__ float g_invdeg[NNET * NN];
__device__ float g_embs[(size_t)NNET * NN * HH];                 // per-net final layer embeddings
__device__ float g_part[128 * HH];

// ---------------- adj fp32 -> fp16 + row-sum (one pass) ----------------
__global__ void prep_adj(const float* __restrict__ adj)
{
    size_t row = blockIdx.x;                 // 0 .. NNET*NN-1
    const float* src = adj + row * NN;
    __half* dst = g_A16 + row * NN;
    int t = threadIdx.x;                     // 256 threads
    float s = 0.f;
#pragma unroll
    for (int i = 0; i < 8; i++) {
        int v4 = t + i * 256;                // float4 index within row (0..2047)
        float4 f = *reinterpret_cast<const float4*>(src + (size_t)v4 * 4);
        s += f.x + f.y + f.z + f.w;
        __half2 h0 = __floats2half2_rn(f.x, f.y);
        __half2 h1 = __floats2half2_rn(f.z, f.w);
        uint2 u;
        u.x = *reinterpret_cast<unsigned*>(&h0);
        u.y = *reinterpret_cast<unsigned*>(&h1);
        *reinterpret_cast<uint2*>(dst + (size_t)v4 * 4) = u;
    }
    // deterministic tree reduce
#pragma unroll
    for (int o = 16; o; o >>= 1) s += __shfl_xor_sync(0xFFFFFFFFu, s, o);
    __shared__ float ws[8];
    int wid = t >> 5, lane = t & 31;
    if (lane == 0) ws[wid] = s;
    __syncthreads();
    if (t == 0) {
        float tot = 0.f;
#pragma unroll
        for (int i = 0; i < 8; i++) tot += ws[i];
        g_invdeg[row] = 1.0f / fmaxf(tot, 1.0f);
    }
}

// ---------------- generic fp32 -> fp16 convert ----------------
__global__ void f2h(const float* __restrict__ src, __half* __restrict__ dst, int n4)
{
    int i = blockIdx.x * blockDim.x + threadIdx.x;
    if (i < n4) {
        float4 f = reinterpret_cast<const float4*>(src)[i];
        __half2 a = __floats2half2_rn(f.x, f.y);
        __half2 b = __floats2half2_rn(f.z, f.w);
        uint2 u;
        u.x = *reinterpret_cast<unsigned*>(&a);
        u.y = *reinterpret_cast<unsigned*>(&b);
        *reinterpret_cast<uint2*>(dst + (size_t)i * 4) = u;
    }
}

// ---------------- comb[:,0:128] = h0_16 ----------------
__global__ void copy_h0()
{
    int i = blockIdx.x * 256 + threadIdx.x;  // vec8 index
    if (i < NN * HH / 8) {
        int n = i >> 4;
        int c = (i & 15) * 8;
        *reinterpret_cast<float4*>(g_comb + (size_t)n * 256 + c) =
            *reinterpret_cast<const float4*>(g_h016 + (size_t)n * 128 + c);
    }
}

// ---------------- fp16 wmma GEMM: C = rowscale .* (A@B) + bias, opt relu ----------------
// A: [M x K] row-major fp16 (M = 8192 always, grid.x = 128, BM = 64)
// B: [K x 128] row-major fp16 (N = 128 always)
// writes fp16 (C16, ldc16) and/or fp32 (C32, ldc32)
__global__ __launch_bounds__(256) void gemm_k(
    const __half* __restrict__ A, int lda,
    const __half* __restrict__ B, int ldb,
    float* __restrict__ C32, int ldc32,
    __half* __restrict__ C16, int ldc16,
    const float* __restrict__ bias,
    const float* __restrict__ rowscale,
    int K, int relu)
{
    constexpr int BM = 64, BN = 128, BK = 64;
    // smem: sA 64x72 halves (9216B), sB 64x136 halves (17408B); sC (64x132 f32 = 33792B) overlays
    __shared__ __align__(16) char sraw[33792];
    __half (*sA)[BK + 8] = reinterpret_cast<__half(*)[BK + 8]>(sraw);
    __half (*sB)[BN + 8] = reinterpret_cast<__half(*)[BN + 8]>(sraw + 9216);
    float* sC = reinterpret_cast<float*>(sraw);   // ld = 132

    int tid = threadIdx.x;
    int wid = tid >> 5;
    int bm = blockIdx.x * BM;
    int wm = (wid >> 2) * 32;
    int wn = (wid & 3) * 32;

    wmma::fragment<wmma::accumulator, 16, 16, 16, float> acc[2][2];
#pragma unroll
    for (int i = 0; i < 2; i++)
#pragma unroll
        for (int j = 0; j < 2; j++)
            wmma::fill_fragment(acc[i][j], 0.0f);

    float4 ra[2], rb[4];
    // initial prefetch (k0 = 0)
#pragma unroll
    for (int i = 0; i < 2; i++) {
        int idx = tid * 8 + i * 2048;
        ra[i] = *reinterpret_cast<const float4*>(A + (size_t)(bm + (idx >> 6)) * lda + (idx & 63));
    }
#pragma unroll
    for (int i = 0; i < 4; i++) {
        int idx = tid * 8 + i * 2048;
        rb[i] = *reinterpret_cast<const float4*>(B + (size_t)(idx >> 7) * ldb + (idx & 127));
    }

    int nk = K >> 6;
    for (int kt = 0; kt < nk; kt++) {
        // stage current tile
#pragma unroll
        for (int i = 0; i < 2; i++) {
            int idx = tid * 8 + i * 2048;
            *reinterpret_cast<float4*>(&sA[idx >> 6][idx & 63]) = ra[i];
        }
#pragma unroll
        for (int i = 0; i < 4; i++) {
            int idx = tid * 8 + i * 2048;
            *reinterpret_cast<float4*>(&sB[idx >> 7][idx & 127]) = rb[i];
        }
        __syncthreads();

        // prefetch next tile (overlaps with mma below)
        if (kt + 1 < nk) {
            int k0 = (kt + 1) << 6;
#pragma unroll
            for (int i = 0; i < 2; i++) {
                int idx = tid * 8 + i * 2048;
                ra[i] = *reinterpret_cast<const float4*>(A + (size_t)(bm + (idx >> 6)) * lda + k0 + (idx & 63));
            }
#pragma unroll
            for (int i = 0; i < 4; i++) {
                int idx = tid * 8 + i * 2048;
                rb[i] = *reinterpret_cast<const float4*>(B + (size_t)(k0 + (idx >> 7)) * ldb + (idx & 127));
            }
        }

#pragma unroll
        for (int kk = 0; kk < BK; kk += 16) {
            wmma::fragment<wmma::matrix_a, 16, 16, 16, __half, wmma::row_major> fa[2];
            wmma::fragment<wmma::matrix_b, 16, 16, 16, __half, wmma::row_major> fb[2];
            wmma::load_matrix_sync(fa[0], &sA[wm][kk], BK + 8);
            wmma::load_matrix_sync(fa[1], &sA[wm + 16][kk], BK + 8);
            wmma::load_matrix_sync(fb[0], &sB[kk][wn], BN + 8);
            wmma::load_matrix_sync(fb[1], &sB[kk][wn + 16], BN + 8);
#pragma unroll
            for (int i = 0; i < 2; i++)
#pragma unroll
                for (int j = 0; j < 2; j++)
                    wmma::mma_sync(acc[i][j], fa[i], fb[j], acc[i][j]);
        }
        __syncthreads();
    }

    // epilogue via smem (known layout)
#pragma unroll
    for (int i = 0; i < 2; i++)
#pragma unroll
        for (int j = 0; j < 2; j++)
            wmma::store_matrix_sync(sC + (size_t)(wm + 16 * i) * 132 + (wn + 16 * j),
                                    acc[i][j], 132, wmma::mem_row_major);
    __syncthreads();

    for (int e = tid; e < BM * BN; e += 256) {
        int r = e >> 7, c = e & 127;
        float vv = sC[r * 132 + c];
        if (rowscale) vv *= rowscale[bm + r];
        if (bias) vv += bias[c];
        if (relu) vv = fmaxf(vv, 0.0f);
        if (C16) C16[(size_t)(bm + r) * ldc16 + c] = __float2half(vv);
        if (C32) C32[(size_t)(bm + r) * ldc32 + c] = vv;
    }
}

// ---------------- attention over layers + output projection ----------------
__global__ __launch_bounds__(256) void attn_out(
    const float* __restrict__ Wa, const float* __restrict__ ba,
    const float* __restrict__ v, const float* __restrict__ Wo,
    const float* __restrict__ bo, float* __restrict__ out)
{
    __shared__ float sWa[HH * 4];
    __shared__ float sba[4], sv[4];
    __shared__ float smix[8][4][132];
    int t = threadIdx.x;
    for (int i = t; i < HH * 4; i += 256) sWa[i] = Wa[i];
    if (t < 4) { sba[t] = ba[t]; sv[t] = v[t]; }
    __syncthreads();

    int w = t >> 5, lane = t & 31;
    for (int q = 0; q < 4; q++) {
        int n = blockIdx.x * 32 + w * 4 + q;
        float e[3][4];
#pragma unroll
        for (int l = 0; l < 3; l++)
#pragma unroll
            for (int ii = 0; ii < 4; ii++)
                e[l][ii] = g_embs[((size_t)l * NN + n) * HH + lane + 32 * ii];

        float sc[3];
#pragma unroll
        for (int l = 0; l < 3; l++) {
            float s = 0.f;
#pragma unroll
            for (int hd = 0; hd < 4; hd++) {
                float d = 0.f;
#pragma unroll
                for (int ii = 0; ii < 4; ii++)
                    d += e[l][ii] * sWa[(lane + 32 * ii) * 4 + hd];
#pragma unroll
                for (int o = 16; o; o >>= 1) d += __shfl_xor_sync(0xFFFFFFFFu, d, o);
                s += tanhf(d + sba[hd]) * sv[hd];
            }
            sc[l] = s;
        }
        float mx = fmaxf(sc[0], fmaxf(sc[1], sc[2]));
        float w0 = expf(sc[0] - mx), w1 = expf(sc[1] - mx), w2 = expf(sc[2] - mx);
        float inv = 1.0f / (w0 + w1 + w2);
        w0 *= inv; w1 *= inv; w2 *= inv;
#pragma unroll
        for (int ii = 0; ii < 4; ii++)
            smix[w][q][lane + 32 * ii] = w0 * e[0][ii] + w1 * e[1][ii] + w2 * e[2][ii];
        __syncwarp();
#pragma unroll
        for (int jj = 0; jj < 4; jj++) {
            int j = lane + 32 * jj;
            float a = bo[j];
            for (int h = 0; h < HH; h++)
                a += smix[w][q][h] * Wo[h * HH + j];     // Wo L1-cached, coalesced
            out[(size_t)n * HH + j] = a;
        }
        __syncwarp();
    }
}

// ---------------- deterministic mean reduction ----------------
__global__ void mean_part(const float* __restrict__ out)
{
    int b = blockIdx.x;       // 128
    int t = threadIdx.x;      // 128
    float s = 0.f;
    for (int r = 0; r < 64; r++)
        s += out[((size_t)b * 64 + r) * HH + t];
    g_part[b * HH + t] = s;
}
__global__ void mean_fin(float* __restrict__ gout)
{
    int t = threadIdx.x;      // 128
    float s = 0.f;
    for (int i = 0; i < 128; i++) s += g_part[i * HH + t];
    gout[t] = s * (1.0f / (float)NN);
}

// ---------------- launcher ----------------
extern "C" void kernel_launch(void* const* d_in, const int* in_sizes, int n_in,
                              void* d_out, int out_size)
{
    (void)in_sizes; (void)n_in; (void)out_size;
    const float* nf  = (const float*)d_in[0];
    const float* adj = (const float*)d_in[1];
    const float* Wi  = (const float*)d_in[2];   (void)Wi;
    const float* bi  = (const float*)d_in[3];
    const float* Wm  = (const float*)d_in[4];   (void)Wm;
    const float* bm  = (const float*)d_in[5];
    const float* Wu  = (const float*)d_in[6];   (void)Wu;
    const float* bu  = (const float*)d_in[7];
    const float* Wa  = (const float*)d_in[8];
    const float* ba  = (const float*)d_in[9];
    const float* v   = (const float*)d_in[10];
    const float* Wo  = (const float*)d_in[11];
    const float* bo  = (const float*)d_in[12];
    float* out = (float*)d_out;

    __half *A16, *X16, *Wi16, *Wm16, *Wu16, *h016, *msg16, *comb;
    float *invdeg, *embs;
    cudaGetSymbolAddress((void**)&A16,   g_A16);
    cudaGetSymbolAddress((void**)&X16,   g_X16);
    cudaGetSymbolAddress((void**)&Wi16,  g_Wi16);
    cudaGetSymbolAddress((void**)&Wm16,  g_Wm16);
    cudaGetSymbolAddress((void**)&Wu16,  g_Wu16);
    cudaGetSymbolAddress((void**)&h016,  g_h016);
    cudaGetSymbolAddress((void**)&msg16, g_msg16);
    cudaGetSymbolAddress((void**)&comb,  g_comb);
    cudaGetSymbolAddress((void**)&invdeg, g_invdeg);
    cudaGetSymbolAddress((void**)&embs,   g_embs);

    // 1. adj -> fp16 + invdeg (one pass over 805MB)
    prep_adj<<<NNET * NN, 256>>>(adj);

    // 2. fp16 conversions of activations/weights
    f2h<<<(NN * IND / 4 + 255) / 256, 256>>>(nf, X16, NN * IND / 4);
    f2h<<<(IND * HH / 4 + 255) / 256, 256>>>(d_in[2] ? (const float*)d_in[2] : nullptr, Wi16, IND * HH / 4);
    f2h<<<(NL * HH * HH / 4 + 255) / 256, 256>>>((const float*)d_in[4], Wm16, NL * HH * HH / 4);
    f2h<<<(NL * 2 * HH * HH / 4 + 255) / 256, 256>>>((const float*)d_in[6], Wu16, NL * 2 * HH * HH / 4);

    // 3. h0 = X @ Wi + bi  (fp16 out)
    gemm_k<<<128, 256>>>(X16, IND, Wi16, HH,
                         nullptr, 0, h016, HH, bi, nullptr, IND, 0);

    // 4. message passing
    for (int net = 0; net < NNET; net++) {
        copy_h0<<<(NN * HH / 8 + 255) / 256, 256>>>();
        for (int l = 0; l < NL; l++) {
            const __half* Bp = (l == 0) ? h016 : comb;
            int ldb = (l == 0) ? HH : 2 * HH;
            // msg = diag(invdeg) * (A @ h)
            gemm_k<<<128, 256>>>(A16 + (size_t)net * NN * NN, NN, Bp, ldb,
                                 nullptr, 0, msg16, HH,
                                 nullptr, invdeg + net * NN, NN, 0);
            // msg2 = msg @ Wm[l] + bm[l]  -> comb[:,128:256]
            gemm_k<<<128, 256>>>(msg16, HH, Wm16 + l * HH * HH, HH,
                                 nullptr, 0, comb + HH, 2 * HH,
                                 bm + l * HH, nullptr, HH, 0);
            // h = relu(comb @ Wu[l] + bu[l]) -> comb[:,0:128] (+fp32 embs if last)
            float* c32 = (l == NL - 1) ? (embs + (size_t)net * NN * HH) : nullptr;
            gemm_k<<<128, 256>>>(comb, 2 * HH, Wu16 + (size_t)l * 2 * HH * HH, HH,
                                 c32, HH, comb, 2 * HH,
                                 bu + l * HH, nullptr, 2 * HH, 1);
        }
    }

    // 5. cross-layer attention + output projection
    attn_out<<<NN / 32, 256>>>(Wa, ba, v, Wo, bo, out);

    // 6. deterministic mean over nodes
    mean_part<<<128, 128>>>(out);
    mean_fin<<<1, 128>>>(out + (size_t)NN * HH);
}

// round 5
// speedup vs baseline: 1.3316x; 1.3316x over previous
#include <cuda_runtime.h>
#include <cuda_fp16.h>
#include <mma.h>
#include <cstdint>
#include <cstddef>

using namespace nvcuda;

#define NN    8192
#define IND   256
#define HH    128
#define NL    3
#define NNET  3

// ---------------- device scratch (static, allowed) ----------------
__device__ __align__(16) __half g_A16[(size_t)NNET * NN * NN];   // 402 MB fp16 adj cache
__device__ __align__(16) __half g_X16[NN * IND];
__device__ __align__(16) __half g_Wi16[IND * HH];
__device__ __align__(16) __half g_Wm16[NL * HH * HH];
__device__ __align__(16) __half g_Wu16[NL * 2 * HH * HH];
__device__ __align__(16) __half g_h016[NN * HH];
__device__ __align__(16) __half g_msg16[NN * HH];
__device__ __align__(16) __half g_comb[NN * 2 * HH];             // [h | msg@Wm] fp16
__device__ __align__(16) float g_ps[2 * NN * HH];                // split-K fp32 partials
__device__ float g_invdeg[NNET * NN];
__device__ float g_embs[(size_t)NNET * NN * HH];                 // per-net final layer embeddings
__device__ float g_part[128 * HH];

// ---------------- helpers ----------------
__device__ __forceinline__ uint32_t s2u(const void* p){
    uint32_t a;
    asm("{ .reg .u64 t; cvta.to.shared.u64 t, %1; cvt.u32.u64 %0, t; }" : "=r"(a) : "l"(p));
    return a;
}
__device__ __forceinline__ void cp16(uint32_t dst, const void* src){
    asm volatile("cp.async.cg.shared.global [%0], [%1], 16;" :: "r"(dst), "l"(src));
}
#define CP_COMMIT() asm volatile("cp.async.commit_group;" ::: "memory")
#define CP_WAIT2()  asm volatile("cp.async.wait_group 2;" ::: "memory")

// =================== pipelined SpMM: part = A[128-rows] @ B  (fp32 partials) ===================
// A: adj fp16 [NN x NN] (one net), B: h fp16 [NN x 128] with row stride ldb.
// grid (64, 2): blockIdx.x = M tile (128 rows), blockIdx.y = K half (4096).
// 4-stage cp.async pipeline, BK=64, 8 warps each computing 32x64.
#define GB_S    4
#define GB_ASZ  (128 * 72 * 2)                  // A stage: 128 rows x (64+8) halves = 18432 B
#define GB_BSZ  (64 * 136 * 2)                  // B stage: 64 rows x (128+8) halves = 17408 B
#define GB_STG  (GB_ASZ + GB_BSZ)               // 35840 B
#define GB_SMEM (GB_S * GB_STG)                 // 143360 B

__global__ __launch_bounds__(256, 1) void gemm_big(
    const __half* __restrict__ A,
    const __half* __restrict__ B, int ldb,
    float* __restrict__ part)
{
    extern __shared__ char dsm[];
    uint32_t sb = s2u(dsm);
    int tid = threadIdx.x;
    int wid = tid >> 5;
    int mt = blockIdx.x, kh = blockIdx.y;
    int bm = mt * 128;
    int kbase = kh * 4096;
    int wm = (wid >> 1) * 32;
    int wn = (wid & 1) * 64;

    // per-thread copy coordinates (4 x 16B for A, 4 x 16B for B per stage)
    // A: idx 0..1023 -> row = idx>>3 (0..127), colgrp = idx&7 (8 halves each)
    // B: idx 0..1023 -> row = idx>>4 (0..63),  colgrp = idx&15
    auto load_stage = [&](int st, int kt) {
        int k0 = kbase + kt * 64;
        uint32_t abase = sb + st * GB_STG;
        uint32_t bbase = abase + GB_ASZ;
#pragma unroll
        for (int i = 0; i < 4; i++) {
            int idx = tid + i * 256;
            int r = idx >> 3, c = idx & 7;
            cp16(abase + r * 144 + c * 16,
                 A + (size_t)(bm + r) * NN + k0 + c * 8);
        }
#pragma unroll
        for (int i = 0; i < 4; i++) {
            int idx = tid + i * 256;
            int r = idx >> 4, c = idx & 15;
            cp16(bbase + r * 272 + c * 16,
                 B + (size_t)(k0 + r) * ldb + c * 8);
        }
    };

    wmma::fragment<wmma::accumulator, 16, 16, 16, float> acc[2][4];
#pragma unroll
    for (int i = 0; i < 2; i++)
#pragma unroll
        for (int j = 0; j < 4; j++)
            wmma::fill_fragment(acc[i][j], 0.0f);

    // prologue: fill 3 stages
#pragma unroll
    for (int s = 0; s < GB_S - 1; s++) { load_stage(s, s); CP_COMMIT(); }

    const int nk = 4096 / 64;
    for (int kt = 0; kt < nk; kt++) {
        CP_WAIT2();
        __syncthreads();
        if (kt + GB_S - 1 < nk) load_stage((kt + GB_S - 1) & (GB_S - 1), kt + GB_S - 1);
        CP_COMMIT();

        int st = kt & (GB_S - 1);
        const __half* pA = reinterpret_cast<const __half*>(dsm + st * GB_STG);
        const __half* pB = reinterpret_cast<const __half*>(dsm + st * GB_STG + GB_ASZ);
#pragma unroll
        for (int kk = 0; kk < 64; kk += 16) {
            wmma::fragment<wmma::matrix_a, 16, 16, 16, __half, wmma::row_major> fa[2];
            wmma::fragment<wmma::matrix_b, 16, 16, 16, __half, wmma::row_major> fb[4];
#pragma unroll
            for (int i = 0; i < 2; i++)
                wmma::load_matrix_sync(fa[i], pA + (size_t)(wm + 16 * i) * 72 + kk, 72);
#pragma unroll
            for (int j = 0; j < 4; j++)
                wmma::load_matrix_sync(fb[j], pB + (size_t)kk * 136 + wn + 16 * j, 136);
#pragma unroll
            for (int i = 0; i < 2; i++)
#pragma unroll
                for (int j = 0; j < 4; j++)
                    wmma::mma_sync(acc[i][j], fa[i], fb[j], acc[i][j]);
        }
        __syncthreads();
    }

    // epilogue: stage accumulators to smem, vectorized fp32 store
    float* sC = reinterpret_cast<float*>(dsm);     // 128 x 132
#pragma unroll
    for (int i = 0; i < 2; i++)
#pragma unroll
        for (int j = 0; j < 4; j++)
            wmma::store_matrix_sync(sC + (size_t)(wm + 16 * i) * 132 + wn + 16 * j,
                                    acc[i][j], 132, wmma::mem_row_major);
    __syncthreads();

    float* out = part + (size_t)kh * NN * HH + (size_t)bm * HH;
    for (int e = tid; e < 128 * 128 / 4; e += 256) {
        int r = e >> 5, c = (e & 31) * 4;
        *reinterpret_cast<float4*>(out + (size_t)r * HH + c) =
            *reinterpret_cast<const float4*>(sC + (size_t)r * 132 + c);
    }
}

// ---------------- combine split-K partials: msg = (p0+p1)*invdeg (fp16) ----------------
__global__ void combine_k(const float* __restrict__ inv)
{
    int i = blockIdx.x * 256 + threadIdx.x;       // float4 group, 0..262143
    const float4* p0 = reinterpret_cast<const float4*>(g_ps);
    const float4* p1 = p0 + (NN * HH / 4);
    float4 a = p0[i], b = p1[i];
    float s = inv[i >> 5];
    __half2 h0 = __floats2half2_rn((a.x + b.x) * s, (a.y + b.y) * s);
    __half2 h1 = __floats2half2_rn((a.z + b.z) * s, (a.w + b.w) * s);
    uint2 u;
    u.x = *reinterpret_cast<unsigned*>(&h0);
    u.y = *reinterpret_cast<unsigned*>(&h1);
    reinterpret_cast<uint2*>(g_msg16)[i] = u;
}

// ---------------- adj fp32 -> fp16 + row-sum (one pass) ----------------
__global__ void prep_adj(const float* __restrict__ adj)
{
    size_t row = blockIdx.x;
    const float* src = adj + row * NN;
    __half* dst = g_A16 + row * NN;
    int t = threadIdx.x;
    float s = 0.f;
#pragma unroll
    for (int i = 0; i < 8; i++) {
        int v4 = t + i * 256;
        float4 f = *reinterpret_cast<const float4*>(src + (size_t)v4 * 4);
        s += f.x + f.y + f.z + f.w;
        __half2 h0 = __floats2half2_rn(f.x, f.y);
        __half2 h1 = __floats2half2_rn(f.z, f.w);
        uint2 u;
        u.x = *reinterpret_cast<unsigned*>(&h0);
        u.y = *reinterpret_cast<unsigned*>(&h1);
        *reinterpret_cast<uint2*>(dst + (size_t)v4 * 4) = u;
    }
#pragma unroll
    for (int o = 16; o; o >>= 1) s += __shfl_xor_sync(0xFFFFFFFFu, s, o);
    __shared__ float ws[8];
    int wid = t >> 5, lane = t & 31;
    if (lane == 0) ws[wid] = s;
    __syncthreads();
    if (t == 0) {
        float tot = 0.f;
#pragma unroll
        for (int i = 0; i < 8; i++) tot += ws[i];
        g_invdeg[row] = 1.0f / fmaxf(tot, 1.0f);
    }
}

// ---------------- generic fp32 -> fp16 convert ----------------
__global__ void f2h(const float* __restrict__ src, __half* __restrict__ dst, int n4)
{
    int i = blockIdx.x * blockDim.x + threadIdx.x;
    if (i < n4) {
        float4 f = reinterpret_cast<const float4*>(src)[i];
        __half2 a = __floats2half2_rn(f.x, f.y);
        __half2 b = __floats2half2_rn(f.z, f.w);
        uint2 u;
        u.x = *reinterpret_cast<unsigned*>(&a);
        u.y = *reinterpret_cast<unsigned*>(&b);
        *reinterpret_cast<uint2*>(dst + (size_t)i * 4) = u;
    }
}

// ---------------- comb[:,0:128] = h0_16 ----------------
__global__ void copy_h0()
{
    int i = blockIdx.x * 256 + threadIdx.x;
    if (i < NN * HH / 8) {
        int n = i >> 4;
        int c = (i & 15) * 8;
        *reinterpret_cast<float4*>(g_comb + (size_t)n * 256 + c) =
            *reinterpret_cast<const float4*>(g_h016 + (size_t)n * 128 + c);
    }
}

// ---------------- fp16 wmma GEMM (small K: projections/updates) ----------------
__global__ __launch_bounds__(256) void gemm_k(
    const __half* __restrict__ A, int lda,
    const __half* __restrict__ B, int ldb,
    float* __restrict__ C32, int ldc32,
    __half* __restrict__ C16, int ldc16,
    const float* __restrict__ bias,
    const float* __restrict__ rowscale,
    int K, int relu)
{
    constexpr int BM = 64, BN = 128, BK = 64;
    __shared__ __align__(16) char sraw[33792];
    __half (*sA)[BK + 8] = reinterpret_cast<__half(*)[BK + 8]>(sraw);
    __half (*sB)[BN + 8] = reinterpret_cast<__half(*)[BN + 8]>(sraw + 9216);
    float* sC = reinterpret_cast<float*>(sraw);

    int tid = threadIdx.x;
    int wid = tid >> 5;
    int bm = blockIdx.x * BM;
    int wm = (wid >> 2) * 32;
    int wn = (wid & 3) * 32;

    wmma::fragment<wmma::accumulator, 16, 16, 16, float> acc[2][2];
#pragma unroll
    for (int i = 0; i < 2; i++)
#pragma unroll
        for (int j = 0; j < 2; j++)
            wmma::fill_fragment(acc[i][j], 0.0f);

    float4 ra[2], rb[4];
#pragma unroll
    for (int i = 0; i < 2; i++) {
        int idx = tid * 8 + i * 2048;
        ra[i] = *reinterpret_cast<const float4*>(A + (size_t)(bm + (idx >> 6)) * lda + (idx & 63));
    }
#pragma unroll
    for (int i = 0; i < 4; i++) {
        int idx = tid * 8 + i * 2048;
        rb[i] = *reinterpret_cast<const float4*>(B + (size_t)(idx >> 7) * ldb + (idx & 127));
    }

    int nk = K >> 6;
    for (int kt = 0; kt < nk; kt++) {
#pragma unroll
        for (int i = 0; i < 2; i++) {
            int idx = tid * 8 + i * 2048;
            *reinterpret_cast<float4*>(&sA[idx >> 6][idx & 63]) = ra[i];
        }
#pragma unroll
        for (int i = 0; i < 4; i++) {
            int idx = tid * 8 + i * 2048;
            *reinterpret_cast<float4*>(&sB[idx >> 7][idx & 127]) = rb[i];
        }
        __syncthreads();

        if (kt + 1 < nk) {
            int k0 = (kt + 1) << 6;
#pragma unroll
            for (int i = 0; i < 2; i++) {
                int idx = tid * 8 + i * 2048;
                ra[i] = *reinterpret_cast<const float4*>(A + (size_t)(bm + (idx >> 6)) * lda + k0 + (idx & 63));
            }
#pragma unroll
            for (int i = 0; i < 4; i++) {
                int idx = tid * 8 + i * 2048;
                rb[i] = *reinterpret_cast<const float4*>(B + (size_t)(k0 + (idx >> 7)) * ldb + (idx & 127));
            }
        }

#pragma unroll
        for (int kk = 0; kk < BK; kk += 16) {
            wmma::fragment<wmma::matrix_a, 16, 16, 16, __half, wmma::row_major> fa[2];
            wmma::fragment<wmma::matrix_b, 16, 16, 16, __half, wmma::row_major> fb[2];
            wmma::load_matrix_sync(fa[0], &sA[wm][kk], BK + 8);
            wmma::load_matrix_sync(fa[1], &sA[wm + 16][kk], BK + 8);
            wmma::load_matrix_sync(fb[0], &sB[kk][wn], BN + 8);
            wmma::load_matrix_sync(fb[1], &sB[kk][wn + 16], BN + 8);
#pragma unroll
            for (int i = 0; i < 2; i++)
#pragma unroll
                for (int j = 0; j < 2; j++)
                    wmma::mma_sync(acc[i][j], fa[i], fb[j], acc[i][j]);
        }
        __syncthreads();
    }

#pragma unroll
    for (int i = 0; i < 2; i++)
#pragma unroll
        for (int j = 0; j < 2; j++)
            wmma::store_matrix_sync(sC + (size_t)(wm + 16 * i) * 132 + (wn + 16 * j),
                                    acc[i][j], 132, wmma::mem_row_major);
    __syncthreads();

    for (int e = tid; e < BM * BN; e += 256) {
        int r = e >> 7, c = e & 127;
        float vv = sC[r * 132 + c];
        if (rowscale) vv *= rowscale[bm + r];
        if (bias) vv += bias[c];
        if (relu) vv = fmaxf(vv, 0.0f);
        if (C16) C16[(size_t)(bm + r) * ldc16 + c] = __float2half(vv);
        if (C32) C32[(size_t)(bm + r) * ldc32 + c] = vv;
    }
}

// ---------------- attention over layers + output projection ----------------
__global__ __launch_bounds__(256) void attn_out(
    const float* __restrict__ Wa, const float* __restrict__ ba,
    const float* __restrict__ v, const float* __restrict__ Wo,
    const float* __restrict__ bo, float* __restrict__ out)
{
    __shared__ float sWa[HH * 4];
    __shared__ float sba[4], sv[4];
    __shared__ float smix[8][4][132];
    int t = threadIdx.x;
    for (int i = t; i < HH * 4; i += 256) sWa[i] = Wa[i];
    if (t < 4) { sba[t] = ba[t]; sv[t] = v[t]; }
    __syncthreads();

    int w = t >> 5, lane = t & 31;
    for (int q = 0; q < 4; q++) {
        int n = blockIdx.x * 32 + w * 4 + q;
        float e[3][4];
#pragma unroll
        for (int l = 0; l < 3; l++)
#pragma unroll
            for (int ii = 0; ii < 4; ii++)
                e[l][ii] = g_embs[((size_t)l * NN + n) * HH + lane + 32 * ii];

        float sc[3];
#pragma unroll
        for (int l = 0; l < 3; l++) {
            float s = 0.f;
#pragma unroll
            for (int hd = 0; hd < 4; hd++) {
                float d = 0.f;
#pragma unroll
                for (int ii = 0; ii < 4; ii++)
                    d += e[l][ii] * sWa[(lane + 32 * ii) * 4 + hd];
#pragma unroll
                for (int o = 16; o; o >>= 1) d += __shfl_xor_sync(0xFFFFFFFFu, d, o);
                s += tanhf(d + sba[hd]) * sv[hd];
            }
            sc[l] = s;
        }
        float mx = fmaxf(sc[0], fmaxf(sc[1], sc[2]));
        float w0 = expf(sc[0] - mx), w1 = expf(sc[1] - mx), w2 = expf(sc[2] - mx);
        float inv = 1.0f / (w0 + w1 + w2);
        w0 *= inv; w1 *= inv; w2 *= inv;
#pragma unroll
        for (int ii = 0; ii < 4; ii++)
            smix[w][q][lane + 32 * ii] = w0 * e[0][ii] + w1 * e[1][ii] + w2 * e[2][ii];
        __syncwarp();
#pragma unroll
        for (int jj = 0; jj < 4; jj++) {
            int j = lane + 32 * jj;
            float a = bo[j];
            for (int h = 0; h < HH; h++)
                a += smix[w][q][h] * Wo[h * HH + j];
            out[(size_t)n * HH + j] = a;
        }
        __syncwarp();
    }
}

// ---------------- deterministic mean reduction ----------------
__global__ void mean_part(const float* __restrict__ out)
{
    int b = blockIdx.x;
    int t = threadIdx.x;
    float s = 0.f;
    for (int r = 0; r < 64; r++)
        s += out[((size_t)b * 64 + r) * HH + t];
    g_part[b * HH + t] = s;
}
__global__ void mean_fin(float* __restrict__ gout)
{
    int t = threadIdx.x;
    float s = 0.f;
    for (int i = 0; i < 128; i++) s += g_part[i * HH + t];
    gout[t] = s * (1.0f / (float)NN);
}

// ---------------- launcher ----------------
extern "C" void kernel_launch(void* const* d_in, const int* in_sizes, int n_in,
                              void* d_out, int out_size)
{
    (void)in_sizes; (void)n_in; (void)out_size;
    const float* nf  = (const float*)d_in[0];
    const float* adj = (const float*)d_in[1];
    const float* bi  = (const float*)d_in[3];
    const float* bm  = (const float*)d_in[5];
    const float* bu  = (const float*)d_in[7];
    const float* Wa  = (const float*)d_in[8];
    const float* ba  = (const float*)d_in[9];
    const float* v   = (const float*)d_in[10];
    const float* Wo  = (const float*)d_in[11];
    const float* bo  = (const float*)d_in[12];
    float* out = (float*)d_out;

    __half *A16, *X16, *Wi16, *Wm16, *Wu16, *h016, *msg16, *comb;
    float *invdeg, *embs, *ps;
    cudaGetSymbolAddress((void**)&A16,   g_A16);
    cudaGetSymbolAddress((void**)&X16,   g_X16);
    cudaGetSymbolAddress((void**)&Wi16,  g_Wi16);
    cudaGetSymbolAddress((void**)&Wm16,  g_Wm16);
    cudaGetSymbolAddress((void**)&Wu16,  g_Wu16);
    cudaGetSymbolAddress((void**)&h016,  g_h016);
    cudaGetSymbolAddress((void**)&msg16, g_msg16);
    cudaGetSymbolAddress((void**)&comb,  g_comb);
    cudaGetSymbolAddress((void**)&invdeg, g_invdeg);
    cudaGetSymbolAddress((void**)&embs,   g_embs);
    cudaGetSymbolAddress((void**)&ps,     g_ps);

    cudaFuncSetAttribute(gemm_big, cudaFuncAttributeMaxDynamicSharedMemorySize, GB_SMEM);

    // 1. adj -> fp16 + invdeg (one pass over 805MB)
    prep_adj<<<NNET * NN, 256>>>(adj);

    // 2. fp16 conversions
    f2h<<<(NN * IND / 4 + 255) / 256, 256>>>(nf, X16, NN * IND / 4);
    f2h<<<(IND * HH / 4 + 255) / 256, 256>>>((const float*)d_in[2], Wi16, IND * HH / 4);
    f2h<<<(NL * HH * HH / 4 + 255) / 256, 256>>>((const float*)d_in[4], Wm16, NL * HH * HH / 4);
    f2h<<<(NL * 2 * HH * HH / 4 + 255) / 256, 256>>>((const float*)d_in[6], Wu16, NL * 2 * HH * HH / 4);

    // 3. h0 = X @ Wi + bi  (fp16 out)
    gemm_k<<<128, 256>>>(X16, IND, Wi16, HH,
                         nullptr, 0, h016, HH, bi, nullptr, IND, 0);

    // 4. message passing (pipelined HMMA SpMM, split-K=2)
    for (int net = 0; net < NNET; net++) {
        copy_h0<<<(NN * HH / 8 + 255) / 256, 256>>>();
        for (int l = 0; l < NL; l++) {
            const __half* Bsrc = (l == 0) ? h016 : comb;
            int ldb = (l == 0) ? HH : 2 * HH;
            // partials = A[net] @ h  (fp32, two K-halves, 128 CTAs)
            gemm_big<<<dim3(NN / 128, 2), 256, GB_SMEM>>>(
                A16 + (size_t)net * NN * NN, Bsrc, ldb, ps);
            // msg = (p0 + p1) * invdeg  (fp16)
            combine_k<<<NN * HH / 4 / 256, 256>>>(invdeg + net * NN);
            // msg2 = msg @ Wm[l] + bm[l]  -> comb[:,128:256]
            gemm_k<<<128, 256>>>(msg16, HH, Wm16 + l * HH * HH, HH,
                                 nullptr, 0, comb + HH, 2 * HH,
                                 bm + l * HH, nullptr, HH, 0);
            // h = relu(comb @ Wu[l] + bu[l]) -> comb[:,0:128] (+fp32 embs if last)
            float* c32 = (l == NL - 1) ? (embs + (size_t)net * NN * HH) : nullptr;
            gemm_k<<<128, 256>>>(comb, 2 * HH, Wu16 + (size_t)l * 2 * HH * HH, HH,
                                 c32, HH, comb, 2 * HH,
                                 bu + l * HH, nullptr, 2 * HH, 1);
        }
    }

    // 5. cross-layer attention + output projection
    attn_out<<<NN / 32, 256>>>(Wa, ba, v, Wo, bo, out);

    // 6. deterministic mean over nodes
    mean_part<<<128, 128>>>(out);
    mean_fin<<<1, 128>>>(out + (size_t)NN * HH);
}